// round 1
// baseline (speedup 1.0000x reference)
#include <cuda_runtime.h>

#define OH 7
#define OW 7
#define CC 8          // channels per block
#define NROWS 14      // 2 corner rows per output row
#define WPAD 66       // max x-span (<= 65) padded

__global__ void roialign_kernel(const float* __restrict__ feat,
                                const int* __restrict__ rois,
                                float* __restrict__ out,
                                int C, int H, int W) {
    __shared__ float s[CC * NROWS * WPAD];
    __shared__ int   srow[NROWS];
    __shared__ int   sxo0[OW], sxo1[OW];
    __shared__ float swy[OH], swx[OW];
    __shared__ int   sWr;

    const int n   = blockIdx.x;
    const int c0  = blockIdx.y * CC;
    const int tid = threadIdx.x;

    const int* r = rois + n * 5;
    const int b  = r[0];
    const int x1 = r[1], y1 = r[2], x2 = r[3], y2 = r[4];

    if (tid < OH) {
        const int j = tid;
        // match reference arithmetic order: coord + j*(delta)/6
        float sy  = (float)y1 + (float)j * (float)(y2 - y1) / 6.0f;
        float y0f = floorf(sy);
        int   iy0 = (int)y0f;
        iy0 = min(max(iy0, 0), H - 1);
        int   iy1 = min(iy0 + 1, H - 1);
        srow[j]      = iy0;
        srow[OH + j] = iy1;
        swy[j]       = sy - y0f;

        float sx  = (float)x1 + (float)j * (float)(x2 - x1) / 6.0f;
        float x0f = floorf(sx);
        int   ix0 = (int)x0f;
        ix0 = min(max(ix0, 0), W - 1);
        int   ix1 = min(ix0 + 1, W - 1);
        sxo0[j] = ix0 - x1;   // offsets relative to staged span start (x1)
        sxo1[j] = ix1 - x1;
        swx[j]  = sx - x0f;
    }
    if (tid == 0) {
        int xhi = min(x2 + 1, W - 1);
        sWr = xhi - x1 + 1;   // staged span width (<= 65)
    }
    __syncthreads();

    const int Wr  = sWr;
    const int xlo = x1;

    // ---- stage: warp per (channel, row), lanes over x (coalesced) ----
    const int warp = tid >> 5, lane = tid & 31;
    const float* fbase = feat + ((size_t)b * C + c0) * (size_t)H * W;
    #pragma unroll 1
    for (int p = warp; p < CC * NROWS; p += 8) {
        const int cl  = p / NROWS;
        const int row = p - cl * NROWS;
        const float* src = fbase + ((size_t)cl * H + srow[row]) * W + xlo;
        float* dst = s + (cl * NROWS + row) * WPAD;
        for (int x = lane; x < Wr; x += 32) dst[x] = __ldg(src + x);
    }
    __syncthreads();

    // ---- compute: bilinear from SMEM, contiguous output writes ----
    float* obase = out + ((size_t)n * C + c0) * (OH * OW);
    #pragma unroll
    for (int k = 0; k < (CC * OH * OW + 255) / 256; k++) {
        const int idx = tid + k * 256;
        if (idx < CC * OH * OW) {
            const int cl  = idx / (OH * OW);
            const int pos = idx - cl * (OH * OW);
            const int oy  = pos / OW;
            const int ox  = pos - oy * OW;
            const float* p0 = s + (cl * NROWS + oy) * WPAD;
            const float* p1 = s + (cl * NROWS + OH + oy) * WPAD;
            const int   xa = sxo0[ox], xb = sxo1[ox];
            const float wy = swy[oy],  wx = swx[ox];
            const float v00 = p0[xa], v01 = p0[xb];
            const float v10 = p1[xa], v11 = p1[xb];
            const float omy = 1.0f - wy, omx = 1.0f - wx;
            obase[idx] = v00 * omy * omx + v01 * omy * wx
                       + v10 * wy  * omx + v11 * wy  * wx;
        }
    }
}

extern "C" void kernel_launch(void* const* d_in, const int* in_sizes, int n_in,
                              void* d_out, int out_size) {
    const float* feat = (const float*)d_in[0];
    const int*   rois = (const int*)d_in[1];
    float*       out  = (float*)d_out;

    const int C = 256, H = 200, W = 200;
    const int N = in_sizes[1] / 5;

    dim3 grid(N, C / CC);
    roialign_kernel<<<grid, 256>>>(feat, rois, out, C, H, W);
}

// round 2
// speedup vs baseline: 1.6331x; 1.6331x over previous
#include <cuda_runtime.h>

#define OH 7
#define OW 7
#define CC 8          // channels per block (== warps per block)
#define NROWS 14      // 2 corner rows per output row
#define NF4MAX 17     // max float4 per staged row (span<=65, +3 align -> 68 floats)
#define WPADF 68      // floats per staged row (17 float4)

__global__ void roialign_kernel(const float* __restrict__ feat,
                                const int* __restrict__ rois,
                                float* __restrict__ out,
                                int C, int H, int W) {
    __shared__ float s[CC * NROWS * WPADF];     // 30464 B
    __shared__ int   srowoff[NROWS];            // srow * W
    __shared__ int   sxo0[OW], sxo1[OW];        // offsets rel. to xlo4
    __shared__ float swy[OH], swx[OW];
    __shared__ int   sNf4, sXlo4;

    const int n   = blockIdx.x;
    const int c0  = blockIdx.y * CC;
    const int tid = threadIdx.x;

    const int* r = rois + n * 5;
    const int b  = r[0];
    const int x1 = r[1], y1 = r[2], x2 = r[3], y2 = r[4];

    const int xlo4 = x1 & ~3;                   // 4-float aligned span start

    if (tid < OH) {
        const int j = tid;
        // y: match reference arithmetic order coord + j*delta/6
        float sy  = (float)y1 + (float)j * (float)(y2 - y1) / 6.0f;
        float y0f = floorf(sy);
        int   iy0 = (int)y0f;
        iy0 = min(max(iy0, 0), H - 1);
        int   iy1 = min(iy0 + 1, H - 1);
        srowoff[j]      = iy0 * W;
        srowoff[OH + j] = iy1 * W;
        swy[j]          = sy - y0f;

        float sx  = (float)x1 + (float)j * (float)(x2 - x1) / 6.0f;
        float x0f = floorf(sx);
        int   ix0 = (int)x0f;
        ix0 = min(max(ix0, 0), W - 1);
        int   ix1 = min(ix0 + 1, W - 1);
        sxo0[j] = ix0 - xlo4;
        sxo1[j] = ix1 - xlo4;
        swx[j]  = sx - x0f;
    }
    if (tid == 0) {
        int xhi   = min(x2 + 1, W - 1);         // last float actually needed
        int nf4   = (xhi - xlo4 + 4) >> 2;      // ceil((xhi - xlo4 + 1)/4)
        int nf4w  = (W - xlo4) >> 2;            // don't read past row end of tensor
        sNf4  = min(nf4, nf4w);
        sXlo4 = xlo4;
    }
    __syncthreads();

    // ---- stage: warp w = channel w; one LDG.128/STS.128 per row ----
    const int warp = tid >> 5, lane = tid & 31;
    const int nf4  = sNf4;
    {
        const float4* src4 = (const float4*)(feat + ((size_t)b * C + c0 + warp) * (size_t)H * W + sXlo4);
        float4* dst4 = (float4*)(s + warp * (NROWS * WPADF));
        #pragma unroll
        for (int row = 0; row < NROWS; row++) {
            if (lane < nf4) {
                dst4[row * NF4MAX + lane] = __ldg(src4 + (srowoff[row] >> 2) + lane);
            }
        }
    }
    __syncthreads();

    // ---- compute: bilinear from SMEM, contiguous output writes ----
    float* obase = out + ((size_t)n * C + c0) * (OH * OW);
    #pragma unroll
    for (int k = 0; k < (CC * OH * OW + 255) / 256; k++) {
        const int idx = tid + k * 256;
        if (idx < CC * OH * OW) {
            const int cl  = idx / (OH * OW);
            const int pos = idx - cl * (OH * OW);
            const int oy  = pos / OW;
            const int ox  = pos - oy * OW;
            const float* p0 = s + (cl * NROWS + oy) * WPADF;
            const float* p1 = s + (cl * NROWS + OH + oy) * WPADF;
            const int   xa = sxo0[ox], xb = sxo1[ox];
            const float wy = swy[oy],  wx = swx[ox];
            const float v00 = p0[xa], v01 = p0[xb];
            const float v10 = p1[xa], v11 = p1[xb];
            const float omy = 1.0f - wy, omx = 1.0f - wx;
            obase[idx] = v00 * omy * omx + v01 * omy * wx
                       + v10 * wy  * omx + v11 * wy  * wx;
        }
    }
}

extern "C" void kernel_launch(void* const* d_in, const int* in_sizes, int n_in,
                              void* d_out, int out_size) {
    const float* feat = (const float*)d_in[0];
    const int*   rois = (const int*)d_in[1];
    float*       out  = (float*)d_out;

    const int C = 256, H = 200, W = 200;
    const int N = in_sizes[1] / 5;

    dim3 grid(N, C / CC);
    roialign_kernel<<<grid, 256>>>(feat, rois, out, C, H, W);
}

// round 3
// speedup vs baseline: 3.1736x; 1.9433x over previous
#include <cuda_runtime.h>
#include <cstdint>

#define OH 7
#define OW 7
#define CC 8           // channels per block (== warps per block)
#define NROWS 14       // 2 corner rows per output row
#define NF4 17         // max float4 per staged row
#define WPADF (NF4*4)  // 68 floats per staged row

__global__ void roialign_kernel(const float* __restrict__ feat,
                                const int* __restrict__ rois,
                                float* __restrict__ out,
                                int C, int H, int W) {
    __shared__ __align__(16) float s[CC * NROWS * WPADF];   // 30464 B
    __shared__ int   sxo0[OW], sxo1[OW];
    __shared__ float swy[OH], swx[OW];

    const int n    = blockIdx.x;
    const int c0   = blockIdx.y * CC;
    const int tid  = threadIdx.x;
    const int warp = tid >> 5, lane = tid & 31;

    const int* r = rois + n * 5;
    const int b  = __ldg(r);
    const int x1 = __ldg(r + 1), y1 = __ldg(r + 2);
    const int x2 = __ldg(r + 3), y2 = __ldg(r + 4);

    // every thread computes span params (cheap, avoids a barrier)
    const int xlo4 = x1 & ~3;
    const int xhi  = min(x2 + 1, W - 1);
    const int nf4  = min((xhi - xlo4 + 4) >> 2, (W - xlo4) >> 2);

    // per-lane row offset: lanes 0..6 hold y0-rows, lanes 7..13 hold y1-rows
    int myrowoff;
    {
        const int jj = (lane < 7) ? lane : lane - 7;
        float sy  = (float)y1 + (float)jj * (float)(y2 - y1) / 6.0f;
        int   iy0 = min(max((int)floorf(sy), 0), H - 1);
        int   iy1 = min(iy0 + 1, H - 1);
        myrowoff = ((lane < 7) ? iy0 : iy1) * W;
    }

    // weights / x-offsets into shared (visible after the single barrier)
    if (tid < OH) {
        const int j = tid;
        float sy  = (float)y1 + (float)j * (float)(y2 - y1) / 6.0f;
        swy[j]    = sy - floorf(sy);
        float sx  = (float)x1 + (float)j * (float)(x2 - x1) / 6.0f;
        float x0f = floorf(sx);
        int   ix0 = min(max((int)x0f, 0), W - 1);
        int   ix1 = min(ix0 + 1, W - 1);
        sxo0[j] = ix0 - xlo4;
        sxo1[j] = ix1 - xlo4;
        swx[j]  = sx - x0f;
    }

    // ---- stage via cp.async: warp = channel, 16 lanes x 2 rows per step ----
    const float* gbase = feat + ((size_t)b * C + c0 + warp) * (size_t)(H * W) + xlo4;
    float* sbase = s + warp * (NROWS * WPADF);
    const int i4  = lane & 15;
    const int rsel = lane >> 4;
    #pragma unroll
    for (int rp = 0; rp < 7; rp++) {
        const int row    = 2 * rp + rsel;
        const int rowoff = __shfl_sync(0xffffffffu, myrowoff, row);
        const float* src = gbase + rowoff + i4 * 4;
        const uint32_t dst =
            (uint32_t)__cvta_generic_to_shared(sbase + row * WPADF + i4 * 4);
        if (i4 < nf4)
            asm volatile("cp.async.cg.shared.global [%0], [%1], 16;\n"
                         :: "r"(dst), "l"(src));
    }
    if (nf4 > 16) {  // rare 17th float4 per row
        const float* src = gbase + myrowoff + 64;
        const uint32_t dst =
            (uint32_t)__cvta_generic_to_shared(sbase + lane * WPADF + 64);
        if (lane < NROWS)
            asm volatile("cp.async.cg.shared.global [%0], [%1], 16;\n"
                         :: "r"(dst), "l"(src));
    }
    asm volatile("cp.async.commit_group;\n" ::: "memory");
    asm volatile("cp.async.wait_group 0;\n" ::: "memory");
    __syncthreads();

    // ---- compute: bilinear from SMEM, contiguous output writes ----
    float* obase = out + ((size_t)n * C + c0) * (OH * OW);
    #pragma unroll
    for (int k = 0; k < (CC * OH * OW + 255) / 256; k++) {
        const int idx = tid + k * 256;
        if (idx < CC * OH * OW) {
            const int cl  = idx / (OH * OW);
            const int pos = idx - cl * (OH * OW);
            const int oy  = pos / OW;
            const int ox  = pos - oy * OW;
            const float* p0 = s + (cl * NROWS + oy) * WPADF;
            const float* p1 = s + (cl * NROWS + OH + oy) * WPADF;
            const int   xa = sxo0[ox], xb = sxo1[ox];
            const float wy = swy[oy],  wx = swx[ox];
            const float v00 = p0[xa], v01 = p0[xb];
            const float v10 = p1[xa], v11 = p1[xb];
            const float omy = 1.0f - wy, omx = 1.0f - wx;
            obase[idx] = v00 * omy * omx + v01 * omy * wx
                       + v10 * wy  * omx + v11 * wy  * wx;
        }
    }
}

extern "C" void kernel_launch(void* const* d_in, const int* in_sizes, int n_in,
                              void* d_out, int out_size) {
    const float* feat = (const float*)d_in[0];
    const int*   rois = (const int*)d_in[1];
    float*       out  = (float*)d_out;

    const int C = 256, H = 200, W = 200;
    const int N = in_sizes[1] / 5;

    dim3 grid(N, C / CC);
    roialign_kernel<<<grid, 256>>>(feat, rois, out, C, H, W);
}

// round 4
// speedup vs baseline: 3.9769x; 1.2531x over previous
#include <cuda_runtime.h>
#include <cstdint>

#define OH 7
#define OW 7
#define CC 8           // channels per block (== warps per block)
#define NROWS 14       // 2 corner rows per output row
#define NF4 17         // max float4 per staged row
#define WPADF (NF4*4)  // 68 floats per staged row

__global__ void roialign_kernel(const float* __restrict__ feat,
                                const int* __restrict__ rois,
                                float* __restrict__ out,
                                int C, int H, int W) {
    __shared__ __align__(16) float s[CC * NROWS * WPADF];   // 30464 B

    const int n    = blockIdx.x;
    const int c0   = blockIdx.y * CC;
    const int tid  = threadIdx.x;
    const int warp = tid >> 5, lane = tid & 31;

    const int* r = rois + n * 5;
    const int b  = __ldg(r);
    const int x1 = __ldg(r + 1), y1 = __ldg(r + 2);
    const int x2 = __ldg(r + 3), y2 = __ldg(r + 4);

    const int xlo4 = x1 & ~3;
    const int xhi  = min(x2 + 1, W - 1);
    const int nf4  = min((xhi - xlo4 + 4) >> 2, (W - xlo4) >> 2);

    const float dy6 = (float)(y2 - y1) * 0.16666667f;
    const float dx6 = (float)(x2 - x1) * 0.16666667f;
    const float y1f = (float)y1, x1f = (float)x1;

    // per-lane staged-row offset: lanes 0..6 -> y0 rows, lanes 7..13 -> y1 rows
    int myrowoff;
    {
        const int jj = (lane < 7) ? lane : lane - 7;
        float sy  = y1f + (float)jj * dy6;
        int   iy0 = min(max((int)floorf(sy), 0), H - 1);
        int   iy1 = min(iy0 + 1, H - 1);
        myrowoff = ((lane < 7) ? iy0 : iy1) * W;
    }

    // ---- stage via cp.async: warp = channel, 16 lanes x 2 rows per step ----
    const float* gbase = feat + ((size_t)b * C + c0 + warp) * (size_t)(H * W) + xlo4;
    float* sbase = s + warp * (NROWS * WPADF);
    {
        const int i4   = lane & 15;
        const int rsel = lane >> 4;
        #pragma unroll
        for (int rp = 0; rp < 7; rp++) {
            const int row    = 2 * rp + rsel;
            const int rowoff = __shfl_sync(0xffffffffu, myrowoff, row);
            const float* src = gbase + rowoff + i4 * 4;
            const uint32_t dst =
                (uint32_t)__cvta_generic_to_shared(sbase + row * WPADF + i4 * 4);
            if (i4 < nf4)
                asm volatile("cp.async.cg.shared.global [%0], [%1], 16;\n"
                             :: "r"(dst), "l"(src));
        }
        if (nf4 > 16) {  // rare 17th float4 per row
            const float* src = gbase + myrowoff + 64;
            const uint32_t dst =
                (uint32_t)__cvta_generic_to_shared(sbase + lane * WPADF + 64);
            if (lane < NROWS)
                asm volatile("cp.async.cg.shared.global [%0], [%1], 16;\n"
                             :: "r"(dst), "l"(src));
        }
        asm volatile("cp.async.commit_group;\n" ::: "memory");
        asm volatile("cp.async.wait_group 0;\n" ::: "memory");
        __syncwarp();
    }

    // ---- compute: warp consumes its own channel; weights inline, no tables ----
    float* obase = out + ((size_t)(n * C + c0 + warp)) * (OH * OW);
    #pragma unroll
    for (int it = 0; it < 2; it++) {
        const int pos = lane + it * 32;
        if (pos < OH * OW) {
            const int oy = (pos * 37) >> 8;        // pos / 7 for pos in [0,48]
            const int ox = pos - oy * 7;

            float sy  = y1f + (float)oy * dy6;
            float y0f = floorf(sy);
            const float wy = sy - y0f;

            float sx  = x1f + (float)ox * dx6;
            float x0f = floorf(sx);
            const float wx = sx - x0f;
            int ix0 = min(max((int)x0f, 0), W - 1);
            int ix1 = min(ix0 + 1, W - 1);
            const int xa = ix0 - xlo4;
            const int xb = ix1 - xlo4;

            const float* p0 = sbase + oy * WPADF;
            const float* p1 = p0 + OH * WPADF;
            const float v00 = p0[xa], v01 = p0[xb];
            const float v10 = p1[xa], v11 = p1[xb];
            const float omy = 1.0f - wy, omx = 1.0f - wx;
            obase[pos] = v00 * omy * omx + v01 * omy * wx
                       + v10 * wy  * omx + v11 * wy  * wx;
        }
    }
}

extern "C" void kernel_launch(void* const* d_in, const int* in_sizes, int n_in,
                              void* d_out, int out_size) {
    const float* feat = (const float*)d_in[0];
    const int*   rois = (const int*)d_in[1];
    float*       out  = (float*)d_out;

    const int C = 256, H = 200, W = 200;
    const int N = in_sizes[1] / 5;

    dim3 grid(N, C / CC);
    roialign_kernel<<<grid, 256>>>(feat, rois, out, C, H, W);
}

// round 5
// speedup vs baseline: 3.9799x; 1.0008x over previous
#include <cuda_runtime.h>
#include <cstdint>

#define OH 7
#define OW 7
#define CC 8           // channels per block (== warps per block)
#define NROWS 14       // 2 corner rows per output row
#define NF4 17         // max float4 chunks per staged row
#define WPADF (NF4*4)  // 68 floats per staged row

__global__ void roialign_kernel(const float* __restrict__ feat,
                                const int* __restrict__ rois,
                                float* __restrict__ out,
                                int C, int H, int W) {
    __shared__ __align__(16) float s[CC * NROWS * WPADF];   // 30464 B

    const int n    = blockIdx.x;
    const int c0   = blockIdx.y * CC;
    const int tid  = threadIdx.x;
    const int warp = tid >> 5, lane = tid & 31;

    const int* r = rois + n * 5;
    const int b  = __ldg(r);
    const int x1 = __ldg(r + 1), y1 = __ldg(r + 2);
    const int x2 = __ldg(r + 3), y2 = __ldg(r + 4);

    const int xlo4 = x1 & ~3;

    const float dy6 = (float)(y2 - y1) * 0.16666667f;
    const float dx6 = (float)(x2 - x1) * 0.16666667f;
    const float y1f = (float)y1, x1f = (float)x1;

    // per-lane staged-row offset: lanes 0..6 -> y0 rows, lanes 7..13 -> y1 rows
    int myrowoff;
    {
        const int jj = (lane < 7) ? lane : lane - 7;
        float sy  = y1f + (float)jj * dy6;
        int   iy0 = min(max((int)floorf(sy), 0), H - 1);
        int   iy1 = min(iy0 + 1, H - 1);
        myrowoff = ((lane < 7) ? iy0 : iy1) * W;
    }

    // 17-bit chunk-need mask: which 16B chunks of the span are actually sampled
    uint32_t mask;
    {
        uint32_t need = 0;
        if (lane < OW) {
            float sx  = x1f + (float)lane * dx6;
            int   ix0 = min(max((int)floorf(sx), 0), W - 1);
            int   ix1 = min(ix0 + 1, W - 1);
            need = (1u << ((ix0 - xlo4) >> 2)) | (1u << ((ix1 - xlo4) >> 2));
        }
        mask = __reduce_or_sync(0xffffffffu, need);
    }

    // ---- stage via cp.async: warp = channel, 16 lanes x 2 rows per step ----
    const float* gbase = feat + ((size_t)b * C + c0 + warp) * (size_t)(H * W) + xlo4;
    float* sbase = s + warp * (NROWS * WPADF);
    {
        const int i4   = lane & 15;
        const int rsel = lane >> 4;
        const bool needme = (mask >> i4) & 1u;
        #pragma unroll
        for (int rp = 0; rp < 7; rp++) {
            const int row    = 2 * rp + rsel;
            const int rowoff = __shfl_sync(0xffffffffu, myrowoff, row);
            const float* src = gbase + rowoff + i4 * 4;
            const uint32_t dst =
                (uint32_t)__cvta_generic_to_shared(sbase + row * WPADF + i4 * 4);
            if (needme)
                asm volatile("cp.async.cg.shared.global [%0], [%1], 16;\n"
                             :: "r"(dst), "l"(src));
        }
        if (mask >> 16) {  // rare 17th chunk
            const float* src = gbase + myrowoff + 64;
            const uint32_t dst =
                (uint32_t)__cvta_generic_to_shared(sbase + lane * WPADF + 64);
            if (lane < NROWS)
                asm volatile("cp.async.cg.shared.global [%0], [%1], 16;\n"
                             :: "r"(dst), "l"(src));
        }
        asm volatile("cp.async.commit_group;\n" ::: "memory");
        asm volatile("cp.async.wait_group 0;\n" ::: "memory");
        __syncwarp();
    }

    // ---- compute: warp consumes its own channel; weights inline ----
    float* obase = out + ((size_t)(n * C + c0 + warp)) * (OH * OW);
    #pragma unroll
    for (int it = 0; it < 2; it++) {
        const int pos = lane + it * 32;
        if (pos < OH * OW) {
            const int oy = (pos * 37) >> 8;        // pos / 7 for pos in [0,48]
            const int ox = pos - oy * 7;

            float sy  = y1f + (float)oy * dy6;
            float y0f = floorf(sy);
            const float wy = sy - y0f;

            float sx  = x1f + (float)ox * dx6;
            float x0f = floorf(sx);
            const float wx = sx - x0f;
            int ix0 = min(max((int)x0f, 0), W - 1);
            int ix1 = min(ix0 + 1, W - 1);
            const int xa = ix0 - xlo4;
            const int xb = ix1 - xlo4;

            const float* p0 = sbase + oy * WPADF;
            const float* p1 = p0 + OH * WPADF;
            const float v00 = p0[xa], v01 = p0[xb];
            const float v10 = p1[xa], v11 = p1[xb];
            const float omy = 1.0f - wy, omx = 1.0f - wx;
            obase[pos] = v00 * omy * omx + v01 * omy * wx
                       + v10 * wy  * omx + v11 * wy  * wx;
        }
    }
}

extern "C" void kernel_launch(void* const* d_in, const int* in_sizes, int n_in,
                              void* d_out, int out_size) {
    const float* feat = (const float*)d_in[0];
    const int*   rois = (const int*)d_in[1];
    float*       out  = (float*)d_out;

    const int C = 256, H = 200, W = 200;
    const int N = in_sizes[1] / 5;

    dim3 grid(N, C / CC);
    roialign_kernel<<<grid, 256>>>(feat, rois, out, C, H, W);
}